// round 12
// baseline (speedup 1.0000x reference)
#include <cuda_runtime.h>
#include <cstdint>

// ---------------------------------------------------------------------------
// Problem constants
// ---------------------------------------------------------------------------
namespace {
constexpr int kB   = 8;
constexpr int kN   = 4096;
constexpr int kE   = 128;   // Din  (GEMM K)
constexpr int kF   = 256;   // Dout (GEMM M)
constexpr int kPTS = 32;    // points per block
constexpr int kM   = 3 * kPTS;  // 96 = GEMM N
constexpr int kT   = 384;   // threads per block (12 warps -> 3 per SMSP)

// smem layout
constexpr int AT_S    = 132;                 // a-tile row stride (f32 words); 132%32=4 -> conflict-free frags
constexpr int OFF_A   = 0;
constexpr int A_BYTES = kM * AT_S * 4;       // 50688
constexpr int W_S     = 36;                  // weight chunk row stride (words): 32 data + 4 pad
constexpr int W_BYTES = kF * W_S * 4;        // 36864
constexpr int OFF_W0  = A_BYTES;             // 50688
constexpr int OFF_W1  = OFF_W0 + W_BYTES;    // 87552
constexpr int RES_S   = 100;                 // result row stride (f32 words)
constexpr int OFF_RX  = OFF_W1 + W_BYTES;    // 124416 (x region, dedicated)
constexpr int OFF_RD  = 0;                   // d region overlays dead a-tile + w-bufs (102400 <= 124416)
constexpr int SMEM_BYTES = OFF_RX + kF * RES_S * 4;   // 226816 B
}

// ---------------------------------------------------------------------------
// Per-launch folded weights (device globals — no allocation allowed)
// ---------------------------------------------------------------------------
__device__ float g_Mc [kF * kE];   // full f32 Mc = A+B+C (for accurate W2 fold)
__device__ float g_McT[kF * kE];   // tf32-rounded Mc
__device__ float g_W2T[kF * kE];   // tf32-rounded W2 = W @ Mc

// ---------------------------------------------------------------------------
// Small helpers
// ---------------------------------------------------------------------------
__device__ __forceinline__ float to_tf32(float v) {
    uint32_t r;
    asm("cvt.rna.tf32.f32 %0, %1;" : "=r"(r) : "f"(v));
    return __uint_as_float(r);
}
__device__ __forceinline__ uint32_t smem_u32(const void* p) {
    uint32_t a;
    asm("{ .reg .u64 t; cvta.to.shared.u64 t, %1; cvt.u32.u64 %0, t; }" : "=r"(a) : "l"(p));
    return a;
}
__device__ __forceinline__ void cp16(uint32_t dst, const float* src) {
    asm volatile("cp.async.cg.shared.global [%0], [%1], 16;"
                 :: "r"(dst), "l"(__cvta_generic_to_global(src)) : "memory");
}
__device__ __forceinline__ void cp_commit() {
    asm volatile("cp.async.commit_group;" ::: "memory");
}
template <int N>
__device__ __forceinline__ void cp_wait() {
    asm volatile("cp.async.wait_group %0;" :: "n"(N) : "memory");
}

// mma.sync m16n8k8 tf32 (sm_80 baseline — compiles under compute_103)
__device__ __forceinline__ void mma_tf32(float (&c)[4], const uint32_t (&a)[4],
                                         const uint32_t (&b)[2]) {
    asm volatile(
        "mma.sync.aligned.m16n8k8.row.col.f32.tf32.tf32.f32 "
        "{%0,%1,%2,%3}, {%4,%5,%6,%7}, {%8,%9}, {%0,%1,%2,%3};"
        : "+f"(c[0]), "+f"(c[1]), "+f"(c[2]), "+f"(c[3])
        : "r"(a[0]), "r"(a[1]), "r"(a[2]), "r"(a[3]), "r"(b[0]), "r"(b[1]));
}

// ---------------------------------------------------------------------------
// Prep kernels
// ---------------------------------------------------------------------------
__global__ void prep_mc(const float* __restrict__ Am, const float* __restrict__ Bm,
                        const float* __restrict__ Cm) {
    const int i = blockIdx.x * 256 + threadIdx.x;
    const float v = Am[i] + Bm[i] + Cm[i];
    g_Mc[i]  = v;
    g_McT[i] = to_tf32(v);
}

__global__ __launch_bounds__(128)
void prep_w2(const float* __restrict__ Wd) {
    __shared__ float wrow[kF];
    const int o = blockIdx.x;
    const int e = threadIdx.x;
    for (int c = threadIdx.x; c < kF; c += 128) wrow[c] = Wd[o * kF + c];
    __syncthreads();
    float acc = 0.0f;
    #pragma unroll 8
    for (int c = 0; c < kF; ++c)
        acc = fmaf(wrow[c], g_Mc[c * kE + e], acc);
    g_W2T[o * kE + e] = to_tf32(acc);
}

// ---------------------------------------------------------------------------
// Pipeline pieces
// ---------------------------------------------------------------------------
// stage one 32-e weight chunk [256 f][32 e] f32 into w buffer (async; 2048 cp16)
__device__ __forceinline__ void issue_chunk(uint32_t sb, int woff,
                                            const float* __restrict__ gsrc,
                                            int eoff, int t) {
    #pragma unroll
    for (int it = 0; it < 6; ++it) {
        const int q = it * kT + t;      // 0..2303, need < 2048
        if (q < 2048) {
            const int f = q >> 3, j = q & 7;
            cp16(sb + woff + f * (W_S * 4) + j * 16,
                 gsrc + (size_t)f * kE + eoff + j * 4);
        }
    }
}

// compute one 32-e chunk: acc[4 tf][4 n][4] += W_chunk x a-tile (tf32)
// warp tile: 64 f-rows (f-quarter) x 32 m (m-third)
__device__ __forceinline__ void compute_chunk(const char* smem, int woff, int eck,
                                              float (&acc)[4][4][4],
                                              int wid, int lane) {
    const int f0w = (wid & 3) * 64;     // f-quarter
    const int mh  = (wid >> 2) * 32;    // m-third
    const int g   = lane >> 2;          // 0..7
    const int k   = lane & 3;           // 0..3
    const uint32_t* as = reinterpret_cast<const uint32_t*>(smem + OFF_A);
    const uint32_t* ws = reinterpret_cast<const uint32_t*>(smem + woff);

    #pragma unroll
    for (int k8 = 0; k8 < 4; ++k8) {
        const int colA = eck * 32 + k8 * 8 + k;   // a-tile global e column

        uint32_t b[4][2];
        #pragma unroll
        for (int n = 0; n < 4; ++n) {
            const int row = (mh + n * 8 + g) * AT_S;
            b[n][0] = as[row + colA];
            b[n][1] = as[row + colA + 4];
        }

        #pragma unroll
        for (int tf = 0; tf < 4; ++tf) {
            const int r0 = (f0w + tf * 16 + g) * W_S;
            const int c0 = k8 * 8 + k;
            uint32_t a[4];
            a[0] = ws[r0 + c0];
            a[1] = ws[r0 + 8 * W_S + c0];
            a[2] = ws[r0 + c0 + 4];
            a[3] = ws[r0 + 8 * W_S + c0 + 4];
            #pragma unroll
            for (int n = 0; n < 4; ++n) mma_tf32(acc[tf][n], a, b[n]);
        }
    }
}

// scatter D-fragment accumulators into res[f][m] (stride RES_S floats)
__device__ __forceinline__ void scatter_acc(char* smem, int res_off,
                                            const float (&acc)[4][4][4],
                                            int wid, int lane) {
    const int f0w  = (wid & 3) * 64;
    const int mh   = (wid >> 2) * 32;
    const int arow = lane >> 2;
    const int acol = (lane & 3) * 2;
    float* res = reinterpret_cast<float*>(smem + res_off);
    #pragma unroll
    for (int tf = 0; tf < 4; ++tf) {
        const int f = f0w + tf * 16 + arow;
        #pragma unroll
        for (int n = 0; n < 4; ++n) {
            const int m = mh + n * 8 + acol;
            *reinterpret_cast<float2*>(res + f * RES_S + m) =
                make_float2(acc[tf][n][0], acc[tf][n][1]);
            *reinterpret_cast<float2*>(res + (f + 8) * RES_S + m) =
                make_float2(acc[tf][n][2], acc[tf][n][3]);
        }
    }
}

// ---------------------------------------------------------------------------
// Main fused kernel
// ---------------------------------------------------------------------------
__global__ __launch_bounds__(kT, 1)
void affine_vn_tf32(const float* __restrict__ X, const float* __restrict__ J,
                    float* __restrict__ out)
{
    extern __shared__ char smem[];
    const uint32_t sb = smem_u32(smem);
    const int t    = threadIdx.x;
    const int wid  = t >> 5;
    const int lane = t & 31;
    const int b    = blockIdx.y;
    const int n0   = blockIdx.x * kPTS;

    // kick off weight chunk 0 (Mc e[0:32)) — streams to smem during phase 1
    issue_chunk(sb, OFF_W0, g_McT, 0, t);
    cp_commit();

    // ---- Phase 1: rotations + projections -> a-tile tf32 [m][e] ----
    float* a_s = reinterpret_cast<float*>(smem + OFF_A);
    #pragma unroll
    for (int it = 0; it < 11; ++it) {
        const int q = it * kT + t;      // need < 4096
        if (q < 4096) {
            const int e  = q & (kE - 1);
            const int nl = q >> 7;
            const size_t base = (size_t)(b * kN + n0 + nl) * kE + e;
            const float* xp = X + base * 3;
            const float* jp = J + base * 6;
            const float x0 = xp[0], x1 = xp[1], x2 = xp[2];
            const float u0 = jp[0], u1 = jp[2], u2 = jp[4];
            const float v0 = jp[1], v1 = jp[3], v2 = jp[5];

            const float nn  = u0*u0 + u1*u1 + u2*u2;
            const float iv1 = rsqrtf(fmaxf(nn, 1e-24f));
            const float b10 = u0*iv1, b11 = u1*iv1, b12 = u2*iv1;
            const float dp  = b10*v0 + b11*v1 + b12*v2;
            const float w0 = v0 - dp*b10, w1 = v1 - dp*b11, w2 = v2 - dp*b12;
            const float wn  = w0*w0 + w1*w1 + w2*w2;
            const float iv2 = rsqrtf(fmaxf(wn, 1e-24f));
            const float b20 = w0*iv2, b21 = w1*iv2, b22 = w2*iv2;
            const float b30 = b11*b22 - b12*b21;
            const float b31 = b12*b20 - b10*b22;
            const float b32 = b10*b21 - b11*b20;

            const int m0 = nl * 3;
            a_s[(m0 + 0) * AT_S + e] = to_tf32(x0*b10 + x1*b11 + x2*b12);
            a_s[(m0 + 1) * AT_S + e] = to_tf32(x0*b20 + x1*b21 + x2*b22);
            a_s[(m0 + 2) * AT_S + e] = to_tf32(x0*b30 + x1*b31 + x2*b32);
        }
    }

    // ---- Phase 2: x = Mc (x) a   (chunks 0..3, double-buffered) ----
    float accx[4][4][4];
    #pragma unroll
    for (int i = 0; i < 4; ++i)
        #pragma unroll
        for (int j = 0; j < 4; ++j)
            #pragma unroll
            for (int q = 0; q < 4; ++q) accx[i][j][q] = 0.0f;

    #pragma unroll
    for (int ck = 0; ck < 4; ++ck) {
        __syncthreads();   // (ck==0: publishes a-tile) buffer (ck+1)&1 free
        if (ck < 3) issue_chunk(sb, ((ck + 1) & 1) ? OFF_W1 : OFF_W0, g_McT, (ck + 1) * 32, t);
        else        issue_chunk(sb, OFF_W0, g_W2T, 0, t);   // prefetch W2 chunk 0
        cp_commit();
        cp_wait<1>();      // chunk ck has landed
        __syncthreads();
        compute_chunk(smem, (ck & 1) ? OFF_W1 : OFF_W0, ck, accx, wid, lane);
    }
    scatter_acc(smem, OFF_RX, accx, wid, lane);   // dedicated region, thread-private: no sync

    // ---- Phase 3: d = W2 (x) a   (chunks 4..7) ----
    float accd[4][4][4];
    #pragma unroll
    for (int i = 0; i < 4; ++i)
        #pragma unroll
        for (int j = 0; j < 4; ++j)
            #pragma unroll
            for (int q = 0; q < 4; ++q) accd[i][j][q] = 0.0f;

    #pragma unroll
    for (int ck = 4; ck < 8; ++ck) {
        __syncthreads();
        if (ck < 7) {
            issue_chunk(sb, ((ck + 1) & 1) ? OFF_W1 : OFF_W0, g_W2T, (ck - 3) * 32, t);
            cp_commit();
            cp_wait<1>();
        } else {
            cp_wait<0>();
        }
        __syncthreads();
        compute_chunk(smem, (ck & 1) ? OFF_W1 : OFF_W0, ck - 4, accd, wid, lane);
    }

    __syncthreads();                        // all warps done with a-tile + w-bufs
    scatter_acc(smem, OFF_RD, accd, wid, lane);   // d overlays dead region
    __syncthreads();

    // ---- Epilogue: VN-LeakyReLU on (x,d) triples + coalesced store [B,F,3,N] ----
    {
        const float* xs_base = reinterpret_cast<const float*>(smem + OFF_RX);
        const float* ds_base = reinterpret_cast<const float*>(smem + OFF_RD);
        #pragma unroll
        for (int r = 0; r < 22; ++r) {
            const int f = r * 12 + wid;     // 12 warps stride the 256 f-rows
            if (f < kF) {
                const float* xs = xs_base + f * RES_S + 3 * lane;  // stride-3: conflict-free
                const float* ds = ds_base + f * RES_S + 3 * lane;
                const float X0 = xs[0], X1 = xs[1], X2 = xs[2];
                const float D0 = ds[0], D1 = ds[1], D2 = ds[2];
                const float dot = X0*D0 + X1*D1 + X2*D2;
                const float dsq = D0*D0 + D1*D1 + D2*D2;
                const float s = (dot >= 0.0f) ? 0.0f
                              : 0.8f * dot * __fdividef(1.0f, dsq + 1e-6f);
                const size_t ob = ((size_t)(b * kF + f) * 3) * kN + n0 + lane;
                out[ob]                  = X0 - s * D0;
                out[ob + kN]             = X1 - s * D1;
                out[ob + 2 * (size_t)kN] = X2 - s * D2;
            }
        }
    }
}

// ---------------------------------------------------------------------------
// Launcher
// ---------------------------------------------------------------------------
extern "C" void kernel_launch(void* const* d_in, const int* in_sizes, int n_in,
                              void* d_out, int out_size) {
    (void)in_sizes; (void)n_in; (void)out_size;
    const float* X  = (const float*)d_in[0];
    const float* J  = (const float*)d_in[1];
    const float* Am = (const float*)d_in[2];
    const float* Bm = (const float*)d_in[3];
    const float* Cm = (const float*)d_in[4];
    const float* Wd = (const float*)d_in[5];
    float* out = (float*)d_out;

    prep_mc<<<(kF * kE) / 256, 256>>>(Am, Bm, Cm);
    prep_w2<<<kF, 128>>>(Wd);

    cudaFuncSetAttribute(affine_vn_tf32,
                         cudaFuncAttributeMaxDynamicSharedMemorySize, SMEM_BYTES);
    dim3 grid(kN / kPTS, kB);
    affine_vn_tf32<<<grid, kT, SMEM_BYTES>>>(X, J, out);
}

// round 14
// speedup vs baseline: 1.0906x; 1.0906x over previous
#include <cuda_runtime.h>
#include <cstdint>

// ---------------------------------------------------------------------------
// Problem constants
// ---------------------------------------------------------------------------
namespace {
constexpr int kB   = 8;
constexpr int kN   = 4096;
constexpr int kE   = 128;   // Din  (GEMM K)
constexpr int kF   = 256;   // Dout (GEMM M)
constexpr int kPTS = 32;    // points per block
constexpr int kM   = 3 * kPTS;  // 96 = GEMM N
constexpr int kT   = 256;   // 8 warps

// smem layout
constexpr int AT_S    = 132;                 // a-tile row stride (words); %32=4 -> conflict-free
constexpr int OFF_A   = 0;
constexpr int A_BYTES = kM * AT_S * 4;       // 50688
constexpr int W_S     = 36;                  // weight chunk row stride (words)
constexpr int W_BYTES = kF * W_S * 4;        // 36864
constexpr int OFF_WA0 = A_BYTES;             // Mc chunk, parity 0
constexpr int OFF_WB0 = OFF_WA0 + W_BYTES;   // W2 chunk, parity 0
constexpr int OFF_WA1 = OFF_WB0 + W_BYTES;   // Mc chunk, parity 1
constexpr int OFF_WB1 = OFF_WA1 + W_BYTES;   // W2 chunk, parity 1
constexpr int SMEM_BYTES = OFF_WB1 + W_BYTES;   // 198144 B
}

// ---------------------------------------------------------------------------
// Per-launch folded weights (device globals — no allocation allowed)
// ---------------------------------------------------------------------------
__device__ float g_Mc [kF * kE];   // full f32 Mc = A+B+C (for accurate W2 fold)
__device__ float g_McT[kF * kE];   // tf32-rounded Mc
__device__ float g_W2T[kF * kE];   // tf32-rounded W2 = W @ Mc

// ---------------------------------------------------------------------------
// Small helpers
// ---------------------------------------------------------------------------
__device__ __forceinline__ float to_tf32(float v) {
    uint32_t r;
    asm("cvt.rna.tf32.f32 %0, %1;" : "=r"(r) : "f"(v));
    return __uint_as_float(r);
}
__device__ __forceinline__ uint32_t smem_u32(const void* p) {
    uint32_t a;
    asm("{ .reg .u64 t; cvta.to.shared.u64 t, %1; cvt.u32.u64 %0, t; }" : "=r"(a) : "l"(p));
    return a;
}
__device__ __forceinline__ void cp16(uint32_t dst, const float* src) {
    asm volatile("cp.async.cg.shared.global [%0], [%1], 16;"
                 :: "r"(dst), "l"(__cvta_generic_to_global(src)) : "memory");
}
__device__ __forceinline__ void cp_commit() {
    asm volatile("cp.async.commit_group;" ::: "memory");
}
template <int N>
__device__ __forceinline__ void cp_wait() {
    asm volatile("cp.async.wait_group %0;" :: "n"(N) : "memory");
}

// mma.sync m16n8k8 tf32 (sm_80 baseline — compiles under compute_103)
__device__ __forceinline__ void mma_tf32(float (&c)[4], const uint32_t (&a)[4],
                                         const uint32_t (&b)[2]) {
    asm volatile(
        "mma.sync.aligned.m16n8k8.row.col.f32.tf32.tf32.f32 "
        "{%0,%1,%2,%3}, {%4,%5,%6,%7}, {%8,%9}, {%0,%1,%2,%3};"
        : "+f"(c[0]), "+f"(c[1]), "+f"(c[2]), "+f"(c[3])
        : "r"(a[0]), "r"(a[1]), "r"(a[2]), "r"(a[3]), "r"(b[0]), "r"(b[1]));
}

// ---------------------------------------------------------------------------
// Prep kernels
// ---------------------------------------------------------------------------
__global__ void prep_mc(const float* __restrict__ Am, const float* __restrict__ Bm,
                        const float* __restrict__ Cm) {
    const int i = blockIdx.x * 256 + threadIdx.x;
    const float v = Am[i] + Bm[i] + Cm[i];
    g_Mc[i]  = v;
    g_McT[i] = to_tf32(v);
}

__global__ __launch_bounds__(128)
void prep_w2(const float* __restrict__ Wd) {
    __shared__ float wrow[kF];
    const int o = blockIdx.x;
    const int e = threadIdx.x;
    for (int c = threadIdx.x; c < kF; c += 128) wrow[c] = Wd[o * kF + c];
    __syncthreads();
    float acc = 0.0f;
    #pragma unroll 8
    for (int c = 0; c < kF; ++c)
        acc = fmaf(wrow[c], g_Mc[c * kE + e], acc);
    g_W2T[o * kE + e] = to_tf32(acc);
}

// ---------------------------------------------------------------------------
// Pipeline pieces
// ---------------------------------------------------------------------------
// stage one (Mc, W2) chunk pair [256 f][32 e] into parity buffers (async)
__device__ __forceinline__ void issue_pair(uint32_t sb, int par, int eoff, int t) {
    const int wa = par ? OFF_WA1 : OFF_WA0;
    const int wb = par ? OFF_WB1 : OFF_WB0;
    #pragma unroll
    for (int it = 0; it < 8; ++it) {
        const int q = it * kT + t;      // 0..2047
        const int f = q >> 3, j = q & 7;
        const size_t gi = (size_t)f * kE + eoff + j * 4;
        const uint32_t so = (uint32_t)(f * (W_S * 4) + j * 16);
        cp16(sb + wa + so, g_McT + gi);
        cp16(sb + wb + so, g_W2T + gi);
    }
}

// compute one 32-e chunk for BOTH GEMMs: B-frags loaded once, two A-frag sets
__device__ __forceinline__ void compute_pair(const char* smem, int par, int eck,
                                             float (&ax)[4][6][4], float (&ad)[4][6][4],
                                             int wid, int lane) {
    const int f0w = (wid & 3) * 64;     // f-quarter
    const int mh  = (wid >> 2) * 48;    // m-half
    const int g   = lane >> 2;          // 0..7
    const int k   = lane & 3;           // 0..3
    const uint32_t* as = reinterpret_cast<const uint32_t*>(smem + OFF_A);
    const uint32_t* wx = reinterpret_cast<const uint32_t*>(smem + (par ? OFF_WA1 : OFF_WA0));
    const uint32_t* wd = reinterpret_cast<const uint32_t*>(smem + (par ? OFF_WB1 : OFF_WB0));

    #pragma unroll
    for (int k8 = 0; k8 < 4; ++k8) {
        const int colA = eck * 32 + k8 * 8 + k;

        uint32_t b[6][2];
        #pragma unroll
        for (int n = 0; n < 6; ++n) {
            const int row = (mh + n * 8 + g) * AT_S;
            b[n][0] = as[row + colA];
            b[n][1] = as[row + colA + 4];
        }

        #pragma unroll
        for (int tf = 0; tf < 4; ++tf) {
            const int r0 = (f0w + tf * 16 + g) * W_S;
            const int c0 = k8 * 8 + k;
            uint32_t a[4];
            a[0] = wx[r0 + c0];
            a[1] = wx[r0 + 8 * W_S + c0];
            a[2] = wx[r0 + c0 + 4];
            a[3] = wx[r0 + 8 * W_S + c0 + 4];
            #pragma unroll
            for (int n = 0; n < 6; ++n) mma_tf32(ax[tf][n], a, b[n]);

            a[0] = wd[r0 + c0];
            a[1] = wd[r0 + 8 * W_S + c0];
            a[2] = wd[r0 + c0 + 4];
            a[3] = wd[r0 + 8 * W_S + c0 + 4];
            #pragma unroll
            for (int n = 0; n < 6; ++n) mma_tf32(ad[tf][n], a, b[n]);
        }
    }
}

// ---------------------------------------------------------------------------
// Main fused kernel
// ---------------------------------------------------------------------------
__global__ __launch_bounds__(kT, 1)
void affine_vn_tf32(const float* __restrict__ X, const float* __restrict__ J,
                    float* __restrict__ out)
{
    extern __shared__ char smem[];
    const uint32_t sb = smem_u32(smem);
    const int t    = threadIdx.x;
    const int wid  = t >> 5;
    const int lane = t & 31;
    const int b    = blockIdx.y;
    const int n0   = blockIdx.x * kPTS;

    // kick off weight chunk pairs 0 and 1 — stream to smem during phase 1
    issue_pair(sb, 0, 0, t);  cp_commit();
    issue_pair(sb, 1, 32, t); cp_commit();

    // ---- Phase 1: rotations + projections -> a-tile tf32 [slot][e] ----
    // point->m permutation so each lane owns complete (i=0,1,2) triples:
    //   p = 16h + 4tt + j ; slot(p,i) = 48h + 8*((3j+i)>>1) + 2tt + ((3j+i)&1)
    float* a_s = reinterpret_cast<float*>(smem + OFF_A);
    #pragma unroll 4
    for (int it = 0; it < 16; ++it) {
        const int q  = it * kT + t;
        const int e  = q & (kE - 1);
        const int p  = q >> 7;          // point 0..31
        const size_t base = (size_t)(b * kN + n0 + p) * kE + e;
        const float* xp = X + base * 3;
        const float* jp = J + base * 6;
        const float x0 = xp[0], x1 = xp[1], x2 = xp[2];
        const float u0 = jp[0], u1 = jp[2], u2 = jp[4];
        const float v0 = jp[1], v1 = jp[3], v2 = jp[5];

        const float nn  = u0*u0 + u1*u1 + u2*u2;
        const float iv1 = rsqrtf(fmaxf(nn, 1e-24f));
        const float b10 = u0*iv1, b11 = u1*iv1, b12 = u2*iv1;
        const float dp  = b10*v0 + b11*v1 + b12*v2;
        const float w0 = v0 - dp*b10, w1 = v1 - dp*b11, w2 = v2 - dp*b12;
        const float wn  = w0*w0 + w1*w1 + w2*w2;
        const float iv2 = rsqrtf(fmaxf(wn, 1e-24f));
        const float b20 = w0*iv2, b21 = w1*iv2, b22 = w2*iv2;
        const float b30 = b11*b22 - b12*b21;
        const float b31 = b12*b20 - b10*b22;
        const float b32 = b10*b21 - b11*b20;

        float av[3];
        av[0] = x0*b10 + x1*b11 + x2*b12;
        av[1] = x0*b20 + x1*b21 + x2*b22;
        av[2] = x0*b30 + x1*b31 + x2*b32;

        const int h  = p >> 4;
        const int qq = p & 15;
        const int tt = qq >> 2;
        const int jj = qq & 3;
        #pragma unroll
        for (int i = 0; i < 3; ++i) {
            const int idx  = 3 * jj + i;
            const int slot = 48 * h + 8 * (idx >> 1) + 2 * tt + (idx & 1);
            a_s[slot * AT_S + e] = to_tf32(av[i]);
        }
    }

    // ---- Fused GEMMs: x = Mc (x) a and d = W2 (x) a, 4 chunk pairs ----
    float accx[4][6][4], accd[4][6][4];
    #pragma unroll
    for (int i = 0; i < 4; ++i)
        #pragma unroll
        for (int j = 0; j < 6; ++j)
            #pragma unroll
            for (int q = 0; q < 4; ++q) { accx[i][j][q] = 0.0f; accd[i][j][q] = 0.0f; }

    cp_wait<1>();        // pair 0 landed (locally)
    __syncthreads();     // a-tile + pair 0 visible to all

    #pragma unroll
    for (int ck = 0; ck < 4; ++ck) {
        compute_pair(smem, ck & 1, ck, accx, accd, wid, lane);
        if (ck < 3) {
            __syncthreads();                    // all warps done reading buf[ck&1]
            if (ck < 2) {
                issue_pair(sb, ck & 1, (ck + 2) * 32, t);
                cp_commit();
                cp_wait<1>();                   // pair ck+1 landed locally
            } else {
                cp_wait<0>();                   // last pair landed locally
            }
            __syncthreads();                    // pair ck+1 visible to all
        }
    }

    // ---- Epilogue: VN-LeakyReLU fully in registers + float4 stores ----
    {
        const int f0w = (wid & 3) * 64;
        const int h   = wid >> 2;
        const int g   = lane >> 2;
        const int tt  = lane & 3;
        #pragma unroll
        for (int tf = 0; tf < 4; ++tf) {
            #pragma unroll
            for (int ch = 0; ch < 2; ++ch) {
                const int f = f0w + tf * 16 + ch * 8 + g;
                float res[3][4];
                #pragma unroll
                for (int j = 0; j < 4; ++j) {
                    float xv[3], dv[3];
                    #pragma unroll
                    for (int i = 0; i < 3; ++i) {
                        const int idx = 3 * j + i;
                        xv[i] = accx[tf][idx >> 1][(idx & 1) + 2 * ch];
                        dv[i] = accd[tf][idx >> 1][(idx & 1) + 2 * ch];
                    }
                    const float dot = xv[0]*dv[0] + xv[1]*dv[1] + xv[2]*dv[2];
                    const float dsq = dv[0]*dv[0] + dv[1]*dv[1] + dv[2]*dv[2];
                    const float s = (dot >= 0.0f) ? 0.0f
                                  : 0.8f * dot * __fdividef(1.0f, dsq + 1e-6f);
                    res[0][j] = xv[0] - s * dv[0];
                    res[1][j] = xv[1] - s * dv[1];
                    res[2][j] = xv[2] - s * dv[2];
                }
                const size_t ob = ((size_t)(b * kF + f) * 3) * kN + n0 + 16 * h + 4 * tt;
                #pragma unroll
                for (int i = 0; i < 3; ++i) {
                    *reinterpret_cast<float4*>(out + ob + (size_t)i * kN) =
                        make_float4(res[i][0], res[i][1], res[i][2], res[i][3]);
                }
            }
        }
    }
}

// ---------------------------------------------------------------------------
// Launcher
// ---------------------------------------------------------------------------
extern "C" void kernel_launch(void* const* d_in, const int* in_sizes, int n_in,
                              void* d_out, int out_size) {
    (void)in_sizes; (void)n_in; (void)out_size;
    const float* X  = (const float*)d_in[0];
    const float* J  = (const float*)d_in[1];
    const float* Am = (const float*)d_in[2];
    const float* Bm = (const float*)d_in[3];
    const float* Cm = (const float*)d_in[4];
    const float* Wd = (const float*)d_in[5];
    float* out = (float*)d_out;

    prep_mc<<<(kF * kE) / 256, 256>>>(Am, Bm, Cm);
    prep_w2<<<kF, 128>>>(Wd);

    cudaFuncSetAttribute(affine_vn_tf32,
                         cudaFuncAttributeMaxDynamicSharedMemorySize, SMEM_BYTES);
    dim3 grid(kN / kPTS, kB);
    affine_vn_tf32<<<grid, kT, SMEM_BYTES>>>(X, J, out);
}

// round 15
// speedup vs baseline: 1.4315x; 1.3125x over previous
#include <cuda_runtime.h>
#include <cuda_fp16.h>
#include <cstdint>

// ---------------------------------------------------------------------------
// Problem constants
// ---------------------------------------------------------------------------
namespace {
constexpr int kB   = 8;
constexpr int kN   = 4096;
constexpr int kE   = 128;   // Din  (GEMM K)
constexpr int kF   = 256;   // Dout (GEMM M)
constexpr int kPTS = 32;    // points per block
constexpr int kM   = 3 * kPTS;  // 96 = GEMM N
constexpr int kT   = 256;   // 8 warps

// smem layout (bytes). fp16 everywhere.
constexpr int AT_B    = 272;                 // a-tile row stride bytes (136 fp16); word stride 68%32=4 -> conflict-free
constexpr int OFF_A   = 0;
constexpr int A_BYTES = kM * AT_B;           // 96*272 = 26112
constexpr int W_B     = 80;                  // weight chunk row stride bytes (40 fp16); word stride 20 -> conflict-free
constexpr int W_BYTES = kF * W_B;            // 20480
constexpr int OFF_WA0 = A_BYTES;             // Mc chunk, parity 0   26112
constexpr int OFF_WB0 = OFF_WA0 + W_BYTES;   // W2 chunk, parity 0   46592
constexpr int OFF_WA1 = OFF_WB0 + W_BYTES;   // Mc chunk, parity 1   67072
constexpr int OFF_WB1 = OFF_WA1 + W_BYTES;   // W2 chunk, parity 1   87552
constexpr int SMEM_BYTES = OFF_WB1 + W_BYTES;   // 108032 B
}

// ---------------------------------------------------------------------------
// Per-launch folded weights (device globals — no allocation allowed)
// ---------------------------------------------------------------------------
__device__ float g_Mc[kF * kE];                       // f32 Mc = A+B+C (accurate W2 fold)
__device__ __align__(16) __half g_McH[kF * kE];       // fp16 Mc
__device__ __align__(16) __half g_W2H[kF * kE];       // fp16 W2 = W @ Mc

// ---------------------------------------------------------------------------
// Small helpers
// ---------------------------------------------------------------------------
__device__ __forceinline__ uint32_t smem_u32(const void* p) {
    uint32_t a;
    asm("{ .reg .u64 t; cvta.to.shared.u64 t, %1; cvt.u32.u64 %0, t; }" : "=r"(a) : "l"(p));
    return a;
}
__device__ __forceinline__ void cp16(uint32_t dst, const void* src) {
    asm volatile("cp.async.cg.shared.global [%0], [%1], 16;"
                 :: "r"(dst), "l"(__cvta_generic_to_global(src)) : "memory");
}
__device__ __forceinline__ void cp_commit() {
    asm volatile("cp.async.commit_group;" ::: "memory");
}
template <int N>
__device__ __forceinline__ void cp_wait() {
    asm volatile("cp.async.wait_group %0;" :: "n"(N) : "memory");
}

// mma.sync m16n8k16 fp16->f32 (sm_80 baseline — compiles under compute_103)
__device__ __forceinline__ void mma_f16(float (&c)[4], const uint32_t (&a)[4],
                                        const uint32_t (&b)[2]) {
    asm volatile(
        "mma.sync.aligned.m16n8k16.row.col.f32.f16.f16.f32 "
        "{%0,%1,%2,%3}, {%4,%5,%6,%7}, {%8,%9}, {%0,%1,%2,%3};"
        : "+f"(c[0]), "+f"(c[1]), "+f"(c[2]), "+f"(c[3])
        : "r"(a[0]), "r"(a[1]), "r"(a[2]), "r"(a[3]), "r"(b[0]), "r"(b[1]));
}

// ---------------------------------------------------------------------------
// Prep kernels
// ---------------------------------------------------------------------------
__global__ void prep_mc(const float* __restrict__ Am, const float* __restrict__ Bm,
                        const float* __restrict__ Cm) {
    const int i = blockIdx.x * 256 + threadIdx.x;
    const float v = Am[i] + Bm[i] + Cm[i];
    g_Mc[i]  = v;
    g_McH[i] = __float2half_rn(v);
}

__global__ __launch_bounds__(128)
void prep_w2(const float* __restrict__ Wd) {
    __shared__ float wrow[kF];
    const int o = blockIdx.x;
    const int e = threadIdx.x;
    for (int c = threadIdx.x; c < kF; c += 128) wrow[c] = Wd[o * kF + c];
    __syncthreads();
    float acc = 0.0f;
    #pragma unroll 8
    for (int c = 0; c < kF; ++c)
        acc = fmaf(wrow[c], g_Mc[c * kE + e], acc);
    g_W2H[o * kE + e] = __float2half_rn(acc);
}

// ---------------------------------------------------------------------------
// Pipeline pieces
// ---------------------------------------------------------------------------
// stage one (Mc, W2) fp16 chunk pair [256 f][32 e] into parity buffers (async)
__device__ __forceinline__ void issue_pair(uint32_t sb, int par, int eoff, int t) {
    const int wa = par ? OFF_WA1 : OFF_WA0;
    const int wb = par ? OFF_WB1 : OFF_WB0;
    #pragma unroll
    for (int it = 0; it < 4; ++it) {
        const int q = it * kT + t;      // 0..1023 : 4 cp16 per f-row (32 fp16 = 64 B)
        const int f = q >> 2, j = q & 3;
        const size_t gi = (size_t)f * kE + eoff + j * 8;   // fp16 elements
        const uint32_t so = (uint32_t)(f * W_B + j * 16);
        cp16(sb + wa + so, g_McH + gi);
        cp16(sb + wb + so, g_W2H + gi);
    }
}

// compute one 32-e chunk for BOTH GEMMs (fp16, 2 K-steps of 16)
__device__ __forceinline__ void compute_pair(const char* smem, int par, int eck,
                                             float (&ax)[4][6][4], float (&ad)[4][6][4],
                                             int wid, int lane) {
    const int f0w = (wid & 3) * 64;     // f-quarter
    const int mh  = (wid >> 2) * 48;    // m-half
    const int g   = lane >> 2;          // 0..7
    const int k   = lane & 3;           // 0..3
    const uint32_t* as = reinterpret_cast<const uint32_t*>(smem + OFF_A);
    const uint32_t* wx = reinterpret_cast<const uint32_t*>(smem + (par ? OFF_WA1 : OFF_WA0));
    const uint32_t* wd = reinterpret_cast<const uint32_t*>(smem + (par ? OFF_WB1 : OFF_WB0));

    #pragma unroll
    for (int kk = 0; kk < 2; ++kk) {
        // B fragments (a-tile): word index = row*68 + eck*16 + kk*8 + k, pair reg +4
        const int cb = eck * 16 + kk * 8 + k;
        uint32_t b[6][2];
        #pragma unroll
        for (int n = 0; n < 6; ++n) {
            const int row = (mh + n * 8 + g) * (AT_B / 4);
            b[n][0] = as[row + cb];
            b[n][1] = as[row + cb + 4];
        }

        const int c0 = kk * 8 + k;      // chunk-local word col
        #pragma unroll
        for (int tf = 0; tf < 4; ++tf) {
            const int r0 = (f0w + tf * 16 + g) * (W_B / 4);
            uint32_t a[4];
            a[0] = wx[r0 + c0];
            a[1] = wx[r0 + 8 * (W_B / 4) + c0];
            a[2] = wx[r0 + c0 + 4];
            a[3] = wx[r0 + 8 * (W_B / 4) + c0 + 4];
            #pragma unroll
            for (int n = 0; n < 6; ++n) mma_f16(ax[tf][n], a, b[n]);

            a[0] = wd[r0 + c0];
            a[1] = wd[r0 + 8 * (W_B / 4) + c0];
            a[2] = wd[r0 + c0 + 4];
            a[3] = wd[r0 + 8 * (W_B / 4) + c0 + 4];
            #pragma unroll
            for (int n = 0; n < 6; ++n) mma_f16(ad[tf][n], a, b[n]);
        }
    }
}

// ---------------------------------------------------------------------------
// Main fused kernel
// ---------------------------------------------------------------------------
__global__ __launch_bounds__(kT, 1)
void affine_vn_f16(const float* __restrict__ X, const float* __restrict__ J,
                   float* __restrict__ out)
{
    extern __shared__ char smem[];
    const uint32_t sb = smem_u32(smem);
    const int t    = threadIdx.x;
    const int wid  = t >> 5;
    const int lane = t & 31;
    const int b    = blockIdx.y;
    const int n0   = blockIdx.x * kPTS;

    // kick off weight chunk pairs 0 and 1 — stream to smem during phase 1
    issue_pair(sb, 0, 0, t);  cp_commit();
    issue_pair(sb, 1, 32, t); cp_commit();

    // ---- Phase 1: rotations + projections -> a-tile fp16 [slot][e] ----
    // point->m permutation so each lane owns complete (i=0,1,2) triples:
    //   p = 16h + 4tt + j ; slot(p,i) = 48h + 8*((3j+i)>>1) + 2tt + ((3j+i)&1)
    __half* a_h = reinterpret_cast<__half*>(smem + OFF_A);
    #pragma unroll 4
    for (int it = 0; it < 16; ++it) {
        const int q  = it * kT + t;
        const int e  = q & (kE - 1);
        const int p  = q >> 7;          // point 0..31
        const size_t base = (size_t)(b * kN + n0 + p) * kE + e;
        const float* xp = X + base * 3;
        const float* jp = J + base * 6;
        const float x0 = xp[0], x1 = xp[1], x2 = xp[2];
        const float u0 = jp[0], u1 = jp[2], u2 = jp[4];
        const float v0 = jp[1], v1 = jp[3], v2 = jp[5];

        const float nn  = u0*u0 + u1*u1 + u2*u2;
        const float iv1 = rsqrtf(fmaxf(nn, 1e-24f));
        const float b10 = u0*iv1, b11 = u1*iv1, b12 = u2*iv1;
        const float dp  = b10*v0 + b11*v1 + b12*v2;
        const float w0 = v0 - dp*b10, w1 = v1 - dp*b11, w2 = v2 - dp*b12;
        const float wn  = w0*w0 + w1*w1 + w2*w2;
        const float iv2 = rsqrtf(fmaxf(wn, 1e-24f));
        const float b20 = w0*iv2, b21 = w1*iv2, b22 = w2*iv2;
        const float b30 = b11*b22 - b12*b21;
        const float b31 = b12*b20 - b10*b22;
        const float b32 = b10*b21 - b11*b20;

        float av[3];
        av[0] = x0*b10 + x1*b11 + x2*b12;
        av[1] = x0*b20 + x1*b21 + x2*b22;
        av[2] = x0*b30 + x1*b31 + x2*b32;

        const int h  = p >> 4;
        const int qq = p & 15;
        const int tt = qq >> 2;
        const int jj = qq & 3;
        #pragma unroll
        for (int i = 0; i < 3; ++i) {
            const int idx  = 3 * jj + i;
            const int slot = 48 * h + 8 * (idx >> 1) + 2 * tt + (idx & 1);
            a_h[slot * (AT_B / 2) + e] = __float2half_rn(av[i]);
        }
    }

    // ---- Fused GEMMs: x = Mc (x) a and d = W2 (x) a, 4 chunk pairs ----
    float accx[4][6][4], accd[4][6][4];
    #pragma unroll
    for (int i = 0; i < 4; ++i)
        #pragma unroll
        for (int j = 0; j < 6; ++j)
            #pragma unroll
            for (int q = 0; q < 4; ++q) { accx[i][j][q] = 0.0f; accd[i][j][q] = 0.0f; }

    cp_wait<1>();        // pair 0 landed (locally)
    __syncthreads();     // a-tile + pair 0 visible to all

    #pragma unroll
    for (int ck = 0; ck < 4; ++ck) {
        compute_pair(smem, ck & 1, ck, accx, accd, wid, lane);
        if (ck < 3) {
            __syncthreads();                    // all warps done reading buf[ck&1]
            if (ck < 2) {
                issue_pair(sb, ck & 1, (ck + 2) * 32, t);
                cp_commit();
                cp_wait<1>();                   // pair ck+1 landed locally
            } else {
                cp_wait<0>();                   // last pair landed locally
            }
            __syncthreads();                    // pair ck+1 visible to all
        }
    }

    // ---- Epilogue: VN-LeakyReLU fully in registers + float4 stores ----
    {
        const int f0w = (wid & 3) * 64;
        const int h   = wid >> 2;
        const int g   = lane >> 2;
        const int tt  = lane & 3;
        #pragma unroll
        for (int tf = 0; tf < 4; ++tf) {
            #pragma unroll
            for (int ch = 0; ch < 2; ++ch) {
                const int f = f0w + tf * 16 + ch * 8 + g;
                float res[3][4];
                #pragma unroll
                for (int j = 0; j < 4; ++j) {
                    float xv[3], dv[3];
                    #pragma unroll
                    for (int i = 0; i < 3; ++i) {
                        const int idx = 3 * j + i;
                        xv[i] = accx[tf][idx >> 1][(idx & 1) + 2 * ch];
                        dv[i] = accd[tf][idx >> 1][(idx & 1) + 2 * ch];
                    }
                    const float dot = xv[0]*dv[0] + xv[1]*dv[1] + xv[2]*dv[2];
                    const float dsq = dv[0]*dv[0] + dv[1]*dv[1] + dv[2]*dv[2];
                    const float s = (dot >= 0.0f) ? 0.0f
                                  : 0.8f * dot * __fdividef(1.0f, dsq + 1e-6f);
                    res[0][j] = xv[0] - s * dv[0];
                    res[1][j] = xv[1] - s * dv[1];
                    res[2][j] = xv[2] - s * dv[2];
                }
                const size_t ob = ((size_t)(b * kF + f) * 3) * kN + n0 + 16 * h + 4 * tt;
                #pragma unroll
                for (int i = 0; i < 3; ++i) {
                    *reinterpret_cast<float4*>(out + ob + (size_t)i * kN) =
                        make_float4(res[i][0], res[i][1], res[i][2], res[i][3]);
                }
            }
        }
    }
}

// ---------------------------------------------------------------------------
// Launcher
// ---------------------------------------------------------------------------
extern "C" void kernel_launch(void* const* d_in, const int* in_sizes, int n_in,
                              void* d_out, int out_size) {
    (void)in_sizes; (void)n_in; (void)out_size;
    const float* X  = (const float*)d_in[0];
    const float* J  = (const float*)d_in[1];
    const float* Am = (const float*)d_in[2];
    const float* Bm = (const float*)d_in[3];
    const float* Cm = (const float*)d_in[4];
    const float* Wd = (const float*)d_in[5];
    float* out = (float*)d_out;

    prep_mc<<<(kF * kE) / 256, 256>>>(Am, Bm, Cm);
    prep_w2<<<kF, 128>>>(Wd);

    cudaFuncSetAttribute(affine_vn_f16,
                         cudaFuncAttributeMaxDynamicSharedMemorySize, SMEM_BYTES);
    dim3 grid(kN / kPTS, kB);
    affine_vn_f16<<<grid, kT, SMEM_BYTES>>>(X, J, out);
}